// round 1
// baseline (speedup 1.0000x reference)
#include <cuda_runtime.h>

// PINN jet-propagation kernel: for each scalar x, push a 5-jet
// (value, d1..d4 w.r.t. x) through 1->8 tanh -> 8 tanh -> 2 linear.
// Outputs per point: [u, u_x, u_xx, w, w_x, w_xx, w_xxx, w_xxxx].

__global__ __launch_bounds__(256)
void pinn_jet_kernel(const float* __restrict__ x,
                     const float* __restrict__ W0, const float* __restrict__ b0,
                     const float* __restrict__ W1, const float* __restrict__ b1,
                     const float* __restrict__ W2, const float* __restrict__ b2,
                     float* __restrict__ out, int n)
{
    __shared__ float sW0[8], sb0[8], sW1[64], sb1[8], sW2[16], sb2[2];
    {
        int t = threadIdx.x;
        if (t < 8)  { sW0[t] = W0[t]; sb0[t] = b0[t]; sb1[t] = b1[t]; }
        if (t < 64) { sW1[t] = W1[t]; }
        if (t < 16) { sW2[t] = W2[t]; }
        if (t < 2)  { sb2[t] = b2[t]; }
    }
    __syncthreads();

    int i = blockIdx.x * blockDim.x + threadIdx.x;
    if (i >= n) return;

    const float xv = x[i];

    // ---- Layer 0: z = W0*x + b0 (scalar input) -> tanh jet ----
    // z0 = w*x + b, z1 = w, z2 = z3 = z4 = 0
    float h0[8], h1[8], h2[8], h3[8], h4[8];
#pragma unroll
    for (int j = 0; j < 8; ++j) {
        float w  = sW0[j];
        float z0 = fmaf(w, xv, sb0[j]);
        float t  = tanhf(z0);
        float s  = 1.0f - t * t;            // t'
        float d2 = -2.0f * t * s;           // t''
        float d3 = s * (6.0f * t * t - 2.0f);           // t'''
        float d4 = t * s * (16.0f - 24.0f * t * t);     // t''''
        float w2 = w * w;
        h0[j] = t;
        h1[j] = s  * w;
        h2[j] = d2 * w2;
        h3[j] = d3 * w2 * w;
        h4[j] = d4 * w2 * w2;
    }

    // ---- Layer 1 (8x8) + tanh jet, with output-layer taps fused in ----
    float u0 = sb2[0], u1 = 0.f, u2 = 0.f;                       // u needs d0..d2
    float v0 = sb2[1], v1 = 0.f, v2 = 0.f, v3 = 0.f, v4 = 0.f;   // w needs d0..d4

#pragma unroll
    for (int j = 0; j < 8; ++j) {
        float z0 = sb1[j], z1 = 0.f, z2 = 0.f, z3 = 0.f, z4 = 0.f;
#pragma unroll
        for (int k = 0; k < 8; ++k) {
            float w = sW1[j * 8 + k];
            z0 = fmaf(w, h0[k], z0);
            z1 = fmaf(w, h1[k], z1);
            z2 = fmaf(w, h2[k], z2);
            z3 = fmaf(w, h3[k], z3);
            z4 = fmaf(w, h4[k], z4);
        }
        float t  = tanhf(z0);
        float s  = 1.0f - t * t;
        float d2 = -2.0f * t * s;
        float d3 = s * (6.0f * t * t - 2.0f);
        float d4 = t * s * (16.0f - 24.0f * t * t);

        float z1_2 = z1 * z1;
        // Faa di Bruno, order 0..4
        float g0 = t;
        float g1 = s * z1;
        float g2 = fmaf(d2, z1_2, s * z2);
        float g3 = d3 * z1_2 * z1 + 3.0f * d2 * z1 * z2 + s * z3;
        float g4 = d4 * z1_2 * z1_2
                 + 6.0f * d3 * z1_2 * z2
                 + d2 * fmaf(3.0f * z2, z2, 4.0f * z1 * z3)
                 + s * z4;

        // fused output-layer accumulation (W2 is [2,8])
        float wu = sW2[j];       // row 0 -> u
        float wv = sW2[8 + j];   // row 1 -> w
        u0 = fmaf(wu, g0, u0);
        u1 = fmaf(wu, g1, u1);
        u2 = fmaf(wu, g2, u2);
        v0 = fmaf(wv, g0, v0);
        v1 = fmaf(wv, g1, v1);
        v2 = fmaf(wv, g2, v2);
        v3 = fmaf(wv, g3, v3);
        v4 = fmaf(wv, g4, v4);
    }

    // ---- Store [u, u_x, u_xx, w, w_x, w_xx, w_xxx, w_xxxx] ----
    float4* op = reinterpret_cast<float4*>(out + (size_t)i * 8);
    op[0] = make_float4(u0, u1, u2, v0);
    op[1] = make_float4(v1, v2, v3, v4);
}

extern "C" void kernel_launch(void* const* d_in, const int* in_sizes, int n_in,
                              void* d_out, int out_size)
{
    const float* x  = (const float*)d_in[0];
    const float* W0 = (const float*)d_in[1];
    const float* b0 = (const float*)d_in[2];
    const float* W1 = (const float*)d_in[3];
    const float* b1 = (const float*)d_in[4];
    const float* W2 = (const float*)d_in[5];
    const float* b2 = (const float*)d_in[6];
    float* out = (float*)d_out;

    int n = in_sizes[0];  // x has N elements (N,1)
    int threads = 256;
    int blocks = (n + threads - 1) / threads;
    pinn_jet_kernel<<<blocks, threads>>>(x, W0, b0, W1, b1, W2, b2, out, n);
}